// round 11
// baseline (speedup 1.0000x reference)
#include <cuda_runtime.h>
#include <cuda_bf16.h>
#include <cstdint>
#include <cstddef>

// Problem constants
#define BB    32
#define DD    512
#define NN    4096
#define KK    64
#define DTILE 64           // d rows per CTA
#define NC    128          // n elements per stage (two 64-n sub-tiles)
#define NITER (NN / NC)    // 32

// Stage buffer (32KB): x sub0 @0, x sub1 @8192, a sub0 @16384, a sub1 @24576
#define STG_BYTES  32768
#define STG_AOFF   16384
#define OFF_ASUM   (2 * STG_BYTES)          // 64 floats
#define SMEM_TOTAL (OFF_ASUM + 256 + 1024)  // + alignment slack

__device__ __forceinline__ uint32_t smem_u32(const void* p) {
    uint32_t a;
    asm("{ .reg .u64 t; cvta.to.shared.u64 t, %1; cvt.u32.u64 %0, t; }" : "=r"(a) : "l"(p));
    return a;
}

__device__ __forceinline__ void sts8(uint32_t addr, uint32_t a, uint32_t b) {
    asm volatile("st.shared.v2.b32 [%0], {%1, %2};" :: "r"(addr), "r"(a), "r"(b) : "memory");
}

__device__ __forceinline__ void sts16(uint32_t addr, float4 v) {
    asm volatile("st.shared.v4.b32 [%0], {%1, %2, %3, %4};"
                 :: "r"(addr), "f"(v.x), "f"(v.y), "f"(v.z), "f"(v.w) : "memory");
}

__device__ __forceinline__ float4 lds16(uint32_t addr) {
    float4 v;
    asm volatile("ld.shared.v4.b32 {%0, %1, %2, %3}, [%4];"
                 : "=f"(v.x), "=f"(v.y), "=f"(v.z), "=f"(v.w) : "r"(addr));
    return v;
}

__device__ __forceinline__ void ldsm4(uint32_t* r, uint32_t addr) {
    asm volatile("ldmatrix.sync.aligned.m8n8.x4.shared.b16 {%0,%1,%2,%3}, [%4];"
                 : "=r"(r[0]), "=r"(r[1]), "=r"(r[2]), "=r"(r[3]) : "r"(addr));
}

__device__ __forceinline__ void mma16816(float* d, const uint32_t* a, uint32_t b0, uint32_t b1) {
    asm volatile(
        "mma.sync.aligned.m16n8k16.row.col.f32.bf16.bf16.f32 "
        "{%0,%1,%2,%3}, {%4,%5,%6,%7}, {%8,%9}, {%0,%1,%2,%3};"
        : "+f"(d[0]), "+f"(d[1]), "+f"(d[2]), "+f"(d[3])
        : "r"(a[0]), "r"(a[1]), "r"(a[2]), "r"(a[3]), "r"(b0), "r"(b1));
}

__device__ __forceinline__ void cvt4(const float4& v, uint32_t& lo, uint32_t& hi) {
    __nv_bfloat162 l = __floats2bfloat162_rn(v.x, v.y);
    __nv_bfloat162 h = __floats2bfloat162_rn(v.z, v.w);
    lo = *reinterpret_cast<uint32_t*>(&l);
    hi = *reinterpret_cast<uint32_t*>(&h);
}

// ---------------------------------------------------------------------------
// R10 datapath with NC=128 stages: halves the iteration count (64 -> 32) so
// the fixed per-iteration latency overhead (~850 cyc/window) is paid half as
// often. A stage is two 64-n sub-tiles with the proven 8KB layout; warp `nh`
// owns one whole sub-tile (4 k-steps). Schedule invariant: nothing in
// iteration `it` consumes iteration-`it` loads (drain regs are 1 iter old,
// WAR-pinned fold; LDG prefetch distance 2 stages). Per CTA (b, dt):
// D[64 d, 64 k] = X @ Abar^T, bf16 mma.sync, fp32 epilogue
// V = wx - a_sum[k]*c[k,d] -> out[d,k,b].
// ---------------------------------------------------------------------------
__global__ void __launch_bounds__(256, 2)
vlad_main(const float* __restrict__ x, const float* __restrict__ ab,
          const float* __restrict__ cmat, float* __restrict__ out) {
    extern __shared__ __align__(16) char smem_raw[];
    const uint32_t sbr = smem_u32(smem_raw);
    const uint32_t sb0 = (sbr + 1023) & ~1023u;
    float* asum_s = reinterpret_cast<float*>(smem_raw + (sb0 - sbr) + OFF_ASUM);

    const int tid  = threadIdx.x;
    const int warp = tid >> 5, lane = tid & 31;
    const int b  = blockIdx.x >> 3;
    const int dt = blockIdx.x & 7;

    const float* xbase = x  + ((size_t)b * DD + (size_t)dt * DTILE) * NN;
    const float* abase = ab + (size_t)b * KK * NN;

    // Loader mapping: 2048 float4 per 32KB tile, 8/thread; ci = tid + 256j ->
    // row = ci>>5 (32 float4 per 128-float row), c4 = ci&31.
    // STS offset: sub-tile (c4>>4)*8192 + swizzled 128B-row offset.
    uint32_t sts_off[8];
#pragma unroll
    for (int j = 0; j < 8; j++) {
        int ci = tid + 256 * j, row = ci >> 5, c4 = ci & 31;
        int sub = c4 >> 4, c = c4 & 15;
        uint32_t off = (uint32_t)((row << 7) + (c << 3));
        sts_off[j] = (uint32_t)(sub << 13) + (off ^ ((off >> 3) & 0x70));
    }

    // Warp decomposition: 2(m) x 2(n) x 2(sub-tile = half of contraction)
    const int wm = (warp & 1) * 32;
    const int wn = ((warp >> 1) & 1) * 32;
    const int nh = warp >> 2;                 // owns sub-tile nh (k-steps 4nh..4nh+3)

    // ldmatrix source offsets (within stage buffer, sub-tile folded in)
    const int g = lane >> 3, r = lane & 7;
    uint32_t offA[2], offB[2];
#pragma unroll
    for (int i = 0; i < 2; i++) {
        int row = wm + i * 16 + (g & 1) * 8 + r;
        uint32_t gk = (uint32_t)((g >> 1) * 16);
        offA[i] = (uint32_t)(row << 7) + (gk ^ (uint32_t)((row & 7) << 4))
                + (uint32_t)(nh << 13);
    }
#pragma unroll
    for (int nb = 0; nb < 2; nb++) {
        int row = wn + nb * 16 + (g >> 1) * 8 + r;
        uint32_t gk = (uint32_t)((g & 1) * 16);
        offB[nb] = (uint32_t)(row << 7) + (gk ^ (uint32_t)((row & 7) << 4))
                 + STG_AOFF + (uint32_t)(nh << 13);
    }

    float4 accv[8];
#pragma unroll
    for (int i = 0; i < 8; i++) accv[i] = make_float4(0.f, 0.f, 0.f, 0.f);
    // asum: a-row handled by thread for piece j is (tid+256j)>>5 = warp + 8j
    float asum_p[8] = {0.f, 0.f, 0.f, 0.f, 0.f, 0.f, 0.f, 0.f};

    float4 xr[8], ar[8];

    // ---- prologue: stage 0 -> smem (folded), stage 1 -> regs ----
#pragma unroll
    for (int j = 0; j < 8; j++) {
        int ci = tid + 256 * j, row = ci >> 5, c4 = ci & 31;
        xr[j] = *reinterpret_cast<const float4*>(xbase + (size_t)row * NN + (c4 << 2));
        ar[j] = *reinterpret_cast<const float4*>(abase + (size_t)row * NN + (c4 << 2));
    }
#pragma unroll
    for (int j = 0; j < 8; j++) {
        uint32_t lo, hi;
        cvt4(xr[j], lo, hi); sts8(sb0 + sts_off[j], lo, hi);
        cvt4(ar[j], lo, hi); sts8(sb0 + STG_AOFF + sts_off[j], lo, hi);
        asum_p[j] += (ar[j].x + ar[j].y) + (ar[j].z + ar[j].w);
    }
#pragma unroll
    for (int j = 0; j < 8; j++) {
        int ci = tid + 256 * j, row = ci >> 5, c4 = ci & 31;
        xr[j] = *reinterpret_cast<const float4*>(xbase + (size_t)row * NN + NC + (c4 << 2));
        ar[j] = *reinterpret_cast<const float4*>(abase + (size_t)row * NN + NC + (c4 << 2));
    }

    for (int it = 0; it < NITER; ++it) {
        __syncthreads();

        // (1) Drain: fold + cvt + STS stage it+1 (regs one iteration old; the
        //     fold reads ar BEFORE the LDG refill redefines it -> never waits).
        if (it + 1 < NITER) {
            const uint32_t ns = sb0 + (uint32_t)((it + 1) & 1) * STG_BYTES;
#pragma unroll
            for (int j = 0; j < 8; j++) {
                asum_p[j] += (ar[j].x + ar[j].y) + (ar[j].z + ar[j].w);
                uint32_t lo, hi;
                cvt4(xr[j], lo, hi); sts8(ns + sts_off[j], lo, hi);
                cvt4(ar[j], lo, hi); sts8(ns + STG_AOFF + sts_off[j], lo, hi);
            }
        }

        // (2) Refill: LDG stage it+2 (consumed at next iteration's drain)
        if (it + 2 < NITER) {
            const int nb2 = (it + 2) * NC;
#pragma unroll
            for (int j = 0; j < 8; j++) {
                int ci = tid + 256 * j, row = ci >> 5, c4 = ci & 31;
                xr[j] = *reinterpret_cast<const float4*>(xbase + (size_t)row * NN + nb2 + (c4 << 2));
                ar[j] = *reinterpret_cast<const float4*>(abase + (size_t)row * NN + nb2 + (c4 << 2));
            }
        }

        // (3) Compute stage it from buf it&1, this warp's sub-tile (4 k-steps)
        const uint32_t bs = sb0 + (uint32_t)(it & 1) * STG_BYTES;
#pragma unroll
        for (int s2 = 0; s2 < 4; s2++) {
            const uint32_t kx = (uint32_t)(s2 << 5);
            uint32_t aF0[4], aF1[4], bF0[4], bF1[4];
            ldsm4(aF0, (bs + offA[0]) ^ kx);
            ldsm4(aF1, (bs + offA[1]) ^ kx);
            ldsm4(bF0, (bs + offB[0]) ^ kx);
            ldsm4(bF1, (bs + offB[1]) ^ kx);
            mma16816(reinterpret_cast<float*>(&accv[0]), aF0, bF0[0], bF0[1]);
            mma16816(reinterpret_cast<float*>(&accv[1]), aF0, bF0[2], bF0[3]);
            mma16816(reinterpret_cast<float*>(&accv[2]), aF0, bF1[0], bF1[1]);
            mma16816(reinterpret_cast<float*>(&accv[3]), aF0, bF1[2], bF1[3]);
            mma16816(reinterpret_cast<float*>(&accv[4]), aF1, bF0[0], bF0[1]);
            mma16816(reinterpret_cast<float*>(&accv[5]), aF1, bF0[2], bF0[3]);
            mma16816(reinterpret_cast<float*>(&accv[6]), aF1, bF1[0], bF1[1]);
            mma16816(reinterpret_cast<float*>(&accv[7]), aF1, bF1[2], bF1[3]);
        }
    }

    // ---- a_sum: piece j's row = warp + 8j, shared by the whole warp ----
#pragma unroll
    for (int j = 0; j < 8; j++) {
#pragma unroll
        for (int o = 1; o < 32; o <<= 1)
            asum_p[j] += __shfl_xor_sync(0xFFFFFFFFu, asum_p[j], o);
    }
    if (lane == 0) {
#pragma unroll
        for (int j = 0; j < 8; j++) asum_s[warp + 8 * j] = asum_p[j];
    }

    // ---- sub-tile (contraction) reduction: warps 4-7 -> warps 0-3 ----
    // Reduction region (16KB at sb0) belongs to buf0; after the it=31 sync all
    // warps only read buf1, so no overlap.
    if (nh == 1) {
#pragma unroll
        for (int j4 = 0; j4 < 8; j4++)
            sts16(sb0 + (uint32_t)(j4 * 2048 + (tid & 127) * 16), accv[j4]);
    }
    __syncthreads();

    if (nh == 0) {
#pragma unroll
        for (int j4 = 0; j4 < 8; j4++) {
            float4 p = lds16(sb0 + (uint32_t)(j4 * 2048 + (tid & 127) * 16));
            accv[j4].x += p.x; accv[j4].y += p.y; accv[j4].z += p.z; accv[j4].w += p.w;
        }

        // ---- epilogue: V = wx - a_sum[k]*c[k,d], out[d,k,b] ----
        const int mrow = lane >> 2, ncol = (lane & 3) * 2;
#pragma unroll
        for (int i = 0; i < 2; i++) {
#pragma unroll
            for (int j = 0; j < 4; j++) {
                const float* ap = reinterpret_cast<const float*>(&accv[i * 4 + j]);
                const int k0 = wn + j * 8 + ncol;
                const int d0 = dt * DTILE + wm + i * 16 + mrow;
                const float as0 = asum_s[k0], as1 = asum_s[k0 + 1];
#pragma unroll
                for (int rr = 0; rr < 2; rr++) {
                    const int d = d0 + rr * 8;
                    float v0 = ap[rr * 2 + 0] - as0 * __ldg(cmat + (size_t)k0 * DD + d);
                    float v1 = ap[rr * 2 + 1] - as1 * __ldg(cmat + (size_t)(k0 + 1) * DD + d);
                    out[(size_t)d * KK * BB + (size_t)k0 * BB + b] = v0;
                    out[(size_t)d * KK * BB + (size_t)(k0 + 1) * BB + b] = v1;
                }
            }
        }
    }
}

extern "C" void kernel_launch(void* const* d_in, const int* in_sizes, int n_in,
                              void* d_out, int out_size) {
    (void)in_sizes; (void)n_in; (void)out_size;
    const float* x  = (const float*)d_in[0];
    const float* ab = (const float*)d_in[1];
    const float* c  = (const float*)d_in[2];
    float* out = (float*)d_out;

    cudaFuncSetAttribute(vlad_main, cudaFuncAttributeMaxDynamicSharedMemorySize, SMEM_TOTAL);
    vlad_main<<<BB * 8, 256, SMEM_TOTAL>>>(x, ab, c, out);
}